// round 1
// baseline (speedup 1.0000x reference)
#include <cuda_runtime.h>
#include <cuda_bf16.h>
#include <math.h>

typedef unsigned long long ull;

// ---------------- constants ----------------
#define T_LEN 512
#define B_SZ  64
#define E_DIM 256
#define H_DIM 256
#define S_ST  64
#define G4H   1024   // 4*H

// ---------------- device scratch ----------------
__device__ float g_xg[2][T_LEN][B_SZ][G4H];     // precomputed x-gates + bias (per chain step)
__device__ float g_scF[T_LEN][B_SZ][S_ST];      // forward score contributions
__device__ float g_scB[T_LEN][B_SZ][S_ST];      // backward score contributions

// ---------------- f32x2 helpers ----------------
__device__ __forceinline__ ull pk2(float x, float y) {
    ull r; asm("mov.b64 %0, {%1,%2};" : "=l"(r) : "f"(x), "f"(y)); return r;
}
__device__ __forceinline__ void upk2(ull v, float& x, float& y) {
    asm("mov.b64 {%0,%1}, %2;" : "=f"(x), "=f"(y) : "l"(v));
}
__device__ __forceinline__ ull fma2_(ull a, ull b, ull c) {
    ull d; asm("fma.rn.f32x2 %0, %1, %2, %3;" : "=l"(d) : "l"(a), "l"(b), "l"(c)); return d;
}
__device__ __forceinline__ ull add2_(ull a, ull b) {
    ull d; asm("add.rn.f32x2 %0, %1, %2;" : "=l"(d) : "l"(a), "l"(b)); return d;
}
__device__ __forceinline__ unsigned smem_u32(const void* p) {
    unsigned a;
    asm("{ .reg .u64 t; cvta.to.shared.u64 t, %1; cvt.u32.u64 %0, t; }" : "=r"(a) : "l"(p));
    return a;
}
__device__ __forceinline__ unsigned mapa_(unsigned addr, unsigned rank) {
    unsigned r; asm("mapa.shared::cluster.u32 %0, %1, %2;" : "=r"(r) : "r"(addr), "r"(rank));
    return r;
}
#define CLUSTER_SYNC() do { \
    asm volatile("barrier.cluster.arrive.aligned;" ::: "memory"); \
    asm volatile("barrier.cluster.wait.aligned;"   ::: "memory"); \
} while (0)

__device__ __forceinline__ float sgm(float x) { return 1.0f / (1.0f + expf(-x)); }

// =====================================================================
// Kernel A: x-gates GEMM.  out[n<1024 -> fwd, n>=1024 -> bwd]
//   xg[dir][s][b][g] = emb[obs[t,b]] . Wih_dir[g,:] + bih[g]+bhh[g]
//   fwd: s = t ; bwd: s = 511 - t  (chain-step order)
// Tiles: BM=128 (t*64+b rows), BN=64 (gate cols), BK=32.  f32x2 micro 8x4.
// =====================================================================
__global__ void __launch_bounds__(256) kA(
    const int* __restrict__ obs, const float* __restrict__ emb,
    const float* __restrict__ WihF, const float* __restrict__ WihB,
    const float* __restrict__ bihF, const float* __restrict__ bhhF,
    const float* __restrict__ bihB, const float* __restrict__ bhhB)
{
    __shared__ float As[32][132];
    __shared__ float Bs[32][68];
    __shared__ int rowidx[128];

    const int tid = threadIdx.x;
    const int mBase = blockIdx.x * 128;
    const int nTile = blockIdx.y;            // 0..31
    const int dir = nTile >> 4;
    const int nBase = (nTile & 15) * 64;     // within [0,1024)
    const float* W = dir ? WihB : WihF;

    if (tid < 128) rowidx[tid] = obs[mBase + tid];
    __syncthreads();

    const int ty = tid >> 4;   // 0..15 row-groups of 8
    const int tx = tid & 15;   // 0..15 col-groups of 4

    ull acc[8][2];
#pragma unroll
    for (int i = 0; i < 8; i++) { acc[i][0] = 0ull; acc[i][1] = 0ull; }

    const int arow = tid >> 3, akq = tid & 7;   // A loader mapping
    const int bn = tid >> 2, bkq = tid & 3;     // B loader mapping

    for (int kt = 0; kt < 8; ++kt) {
        // load A tile (gathered embedding rows), store K-major
#pragma unroll
        for (int rr = 0; rr < 4; ++rr) {
            int r = arow + rr * 32;
            const float4 v = *reinterpret_cast<const float4*>(
                &emb[(size_t)rowidx[r] * E_DIM + kt * 32 + akq * 4]);
            As[akq * 4 + 0][r] = v.x; As[akq * 4 + 1][r] = v.y;
            As[akq * 4 + 2][r] = v.z; As[akq * 4 + 3][r] = v.w;
        }
        // load B tile (Wih transposed -> K-major)
#pragma unroll
        for (int hh = 0; hh < 2; ++hh) {
            const float4 v = *reinterpret_cast<const float4*>(
                &W[(size_t)(nBase + bn) * E_DIM + kt * 32 + bkq * 8 + hh * 4]);
            Bs[bkq * 8 + hh * 4 + 0][bn] = v.x; Bs[bkq * 8 + hh * 4 + 1][bn] = v.y;
            Bs[bkq * 8 + hh * 4 + 2][bn] = v.z; Bs[bkq * 8 + hh * 4 + 3][bn] = v.w;
        }
        __syncthreads();
#pragma unroll 8
        for (int k = 0; k < 32; ++k) {
            float4 a0 = *reinterpret_cast<const float4*>(&As[k][ty * 8]);
            float4 a1 = *reinterpret_cast<const float4*>(&As[k][ty * 8 + 4]);
            float4 b4 = *reinterpret_cast<const float4*>(&Bs[k][tx * 4]);
            ull b01 = pk2(b4.x, b4.y), b23 = pk2(b4.z, b4.w);
            float av[8] = {a0.x, a0.y, a0.z, a0.w, a1.x, a1.y, a1.z, a1.w};
#pragma unroll
            for (int i = 0; i < 8; ++i) {
                ull aa = pk2(av[i], av[i]);
                acc[i][0] = fma2_(aa, b01, acc[i][0]);
                acc[i][1] = fma2_(aa, b23, acc[i][1]);
            }
        }
        __syncthreads();
    }

    // epilogue: +bias, scatter (fwd as-is, bwd time-reversed)
    const int n0 = nBase + tx * 4;
    const float* bi = dir ? bihB : bihF;
    const float* bh = dir ? bhhB : bhhF;
    float bias0 = bi[n0 + 0] + bh[n0 + 0];
    float bias1 = bi[n0 + 1] + bh[n0 + 1];
    float bias2 = bi[n0 + 2] + bh[n0 + 2];
    float bias3 = bi[n0 + 3] + bh[n0 + 3];
#pragma unroll
    for (int i = 0; i < 8; ++i) {
        int mg = mBase + ty * 8 + i;
        int t = mg >> 6, b = mg & 63;
        int sIdx = dir ? (T_LEN - 1 - t) : t;
        float x0, x1, x2, x3;
        upk2(acc[i][0], x0, x1); upk2(acc[i][1], x2, x3);
        float4 o = make_float4(x0 + bias0, x1 + bias1, x2 + bias2, x3 + bias3);
        *reinterpret_cast<float4*>(&g_xg[dir][sIdx][b][n0]) = o;
    }
}

// =====================================================================
// Kernel B: recurrence.  16 clusters of 8 CTAs (2 dirs x 8 batch-groups).
// Each CTA: Whh slice (128 gate rows for 32 hidden units) resident in SMEM,
// 8 batches. h exchanged per step via DSMEM + 1 cluster barrier.
// Score contributions (8 states x 8 batches per CTA) fused after exchange.
// =====================================================================
struct SmemB {
    float Ws[256][128];     // Whh slice, K-major              131072 B
    float hbuf[2][256][8];  // full h, [k][batch], ping-pong    16384 B
    float gred[128][8];     // k-half reduction / score partials 4096 B
    float gfull[128][8];    // assembled gates                   4096 B
    float hstage[32][8];    // new h slice staging               1024 B
    float Wl[256][8];       // W_lin slice, K-major              8192 B
};

__global__ void __launch_bounds__(256, 1) __cluster_dims__(8, 1, 1) kB(
    const float* __restrict__ WhhF, const float* __restrict__ WhhB,
    const float* __restrict__ h0, const float* __restrict__ c0,
    const float* __restrict__ Wlin)
{
    extern __shared__ char smraw[];
    SmemB& sm = *reinterpret_cast<SmemB*>(smraw);

    const int tid = threadIdx.x;
    const int blk = blockIdx.x;
    const int cr = blk & 7;            // cluster rank -> owns units [32cr,32cr+32)
    const int cid = blk >> 3;          // 0..15
    const int dir = cid >> 3;          // 0 fwd, 1 bwd
    const int b0 = (cid & 7) * 8;      // batch group base
    const float* Whh = dir ? WhhB : WhhF;
    const float* xg = &g_xg[dir][0][0][0];
    float* scout = dir ? &g_scB[0][0][0] : &g_scF[0][0][0];

    // --- init Whh slice, K-major ---
    for (int idx = tid; idx < 128 * 64; idx += 256) {
        int j = idx >> 6, k4 = idx & 63;
        int rg = ((j >> 5) << 8) + (cr << 5) + (j & 31);   // global gate row
        const float4 v = *reinterpret_cast<const float4*>(&Whh[(size_t)rg * H_DIM + (k4 << 2)]);
        sm.Ws[k4 * 4 + 0][j] = v.x; sm.Ws[k4 * 4 + 1][j] = v.y;
        sm.Ws[k4 * 4 + 2][j] = v.z; sm.Ws[k4 * 4 + 3][j] = v.w;
    }
    // --- init h0 ---
    for (int idx = tid; idx < 2048; idx += 256) {
        int k = idx >> 3, bb = idx & 7;
        sm.hbuf[0][k][bb] = h0[((size_t)dir * B_SZ + b0 + bb) * H_DIM + k];
    }
    // --- init W_lin slice (states 8cr..8cr+7), K-major ---
    for (int idx = tid; idx < 2048; idx += 256) {
        int k = idx >> 3, ss = idx & 7;
        sm.Wl[k][ss] = Wlin[((size_t)(8 * cr + ss)) * (2 * H_DIM) + dir * H_DIM + k];
    }
    // c state in registers: thread owns (u = tid>>3, bb = tid&7)
    const int u = tid >> 3, bb = tid & 7;
    float c_reg = c0[((size_t)dir * B_SZ + b0 + bb) * H_DIM + cr * 32 + u];

    __syncthreads();
    CLUSTER_SYNC();

    const int w = tid >> 5, l = tid & 31;
    const int j = ((w & 3) << 5) + l;          // local gate row 0..127
    const int kbase = (w >> 2) << 7;           // 0 or 128
    const int rg = ((w & 3) << 8) + (cr << 5) + l;  // global gate row (for xg)

    for (int s = 0; s < T_LEN; ++s) {
        const int p = s & 1, q = p ^ 1;

        // xg loads for this step (only combining warps use them)
        float xv[8];
        if (kbase == 0) {
            const float* xgp = xg + ((size_t)s * B_SZ + b0) * G4H + rg;
#pragma unroll
            for (int i = 0; i < 8; ++i) xv[i] = xgp[(size_t)i * G4H];
        }

        // GEMV over half-K: gates[j][b] partial
        ull acc0 = 0, acc1 = 0, acc2 = 0, acc3 = 0;
#pragma unroll 4
        for (int k = 0; k < 128; ++k) {
            float wv = sm.Ws[kbase + k][j];
            ull w2 = pk2(wv, wv);
            const ull* hp = reinterpret_cast<const ull*>(&sm.hbuf[p][kbase + k][0]);
            acc0 = fma2_(w2, hp[0], acc0);
            acc1 = fma2_(w2, hp[1], acc1);
            acc2 = fma2_(w2, hp[2], acc2);
            acc3 = fma2_(w2, hp[3], acc3);
        }
        if (kbase) {
            ull* g = reinterpret_cast<ull*>(&sm.gred[j][0]);
            g[0] = acc0; g[1] = acc1; g[2] = acc2; g[3] = acc3;
        }
        __syncthreads();
        if (!kbase) {
            const ull* g = reinterpret_cast<const ull*>(&sm.gred[j][0]);
            acc0 = add2_(acc0, g[0]); acc1 = add2_(acc1, g[1]);
            acc2 = add2_(acc2, g[2]); acc3 = add2_(acc3, g[3]);
            acc0 = add2_(acc0, pk2(xv[0], xv[1]));
            acc1 = add2_(acc1, pk2(xv[2], xv[3]));
            acc2 = add2_(acc2, pk2(xv[4], xv[5]));
            acc3 = add2_(acc3, pk2(xv[6], xv[7]));
            ull* gf = reinterpret_cast<ull*>(&sm.gfull[j][0]);
            gf[0] = acc0; gf[1] = acc1; gf[2] = acc2; gf[3] = acc3;
        }
        __syncthreads();

        // elementwise LSTM cell for owned (u, bb)
        {
            float gi = sm.gfull[u][bb];
            float gf = sm.gfull[32 + u][bb];
            float gg = sm.gfull[64 + u][bb];
            float go = sm.gfull[96 + u][bb];
            float cc = sgm(gf) * c_reg + sgm(gi) * tanhf(gg);
            c_reg = cc;
            sm.hstage[u][bb] = sgm(go) * tanhf(cc);
        }
        __syncthreads();

        // DSMEM push of h slice to all 8 CTAs (incl. self)
        if (tid < 64) {
            int uu = tid >> 1, half = tid & 1;
            const float4 v = *reinterpret_cast<const float4*>(&sm.hstage[uu][half * 4]);
            unsigned la = smem_u32(&sm.hbuf[q][cr * 32 + uu][half * 4]);
#pragma unroll
            for (int tg = 0; tg < 8; ++tg) {
                unsigned ra = mapa_(la, (unsigned)tg);
                asm volatile("st.shared::cluster.v4.f32 [%0], {%1,%2,%3,%4};"
                             :: "r"(ra), "f"(v.x), "f"(v.y), "f"(v.z), "f"(v.w) : "memory");
            }
        }
        CLUSTER_SYNC();

        // fused emission-score slice: states [8cr,8cr+8), from full new h
        {
            int pair = tid & 63, kq = tid >> 6;
            int ss = pair >> 3, sb = pair & 7;
            int k0 = kq << 6;
            float a = 0.f;
#pragma unroll 4
            for (int k = 0; k < 64; ++k)
                a += sm.hbuf[q][k0 + k][sb] * sm.Wl[k0 + k][ss];
            sm.gred[pair][kq] = a;
        }
        __syncthreads();
        if (tid < 64) {
            float r = sm.gred[tid][0] + sm.gred[tid][1] + sm.gred[tid][2] + sm.gred[tid][3];
            int ss2 = tid >> 3, sb2 = tid & 7;
            int tOut = dir ? (T_LEN - 1 - s) : s;
            scout[((size_t)tOut * B_SZ + b0 + sb2) * S_ST + cr * 8 + ss2] = r;
        }
        __syncthreads();
    }
}

// =====================================================================
// Kernel C: Viterbi DP + backtrace. One CTA per batch, bp kept in SMEM.
// =====================================================================
__global__ void __launch_bounds__(64) kC(
    const float* __restrict__ blin, const float* __restrict__ pw,
    const float* __restrict__ startv, const float* __restrict__ stopv,
    float* __restrict__ out)
{
    extern __shared__ char smc[];
    float* P = reinterpret_cast<float*>(smc);              // 64*64
    float* delta = P + 4096;                               // 64
    float* fin = delta + 64;                               // 64
    unsigned char* bp = reinterpret_cast<unsigned char*>(fin + 64); // 511*64

    const int b = blockIdx.x;
    const int tid = threadIdx.x;

    for (int i = tid; i < 4096; i += 64) P[i] = pw[i];
    const float bl = blin[tid];
    delta[tid] = startv[tid] + g_scF[0][b][tid] + g_scB[0][b][tid] + bl;
    __syncthreads();

    float sF = g_scF[1][b][tid], sB = g_scB[1][b][tid];
    for (int t = 1; t < T_LEN; ++t) {
        const float sc = sF + sB + bl;
        if (t < T_LEN - 1) { sF = g_scF[t + 1][b][tid]; sB = g_scB[t + 1][b][tid]; }
        float best = -3.0e38f; int bi = 0;
#pragma unroll 8
        for (int pv = 0; pv < 64; ++pv) {
            float v = delta[pv] + P[pv * 64 + tid];
            if (v > best) { best = v; bi = pv; }   // strict > : first-max, matches jnp.argmax
        }
        bp[(t - 1) * 64 + tid] = (unsigned char)bi;
        __syncthreads();
        delta[tid] = best + sc;
        __syncthreads();
    }

    fin[tid] = delta[tid] + stopv[tid];
    __syncthreads();
    if (tid == 0) {
        float best = fin[0]; int bi = 0;
        for (int i = 1; i < 64; ++i) if (fin[i] > best) { best = fin[i]; bi = i; }
        out[b] = best;
        int st = bi;
        out[64 + (size_t)(T_LEN - 1) * B_SZ + b] = (float)st;
        for (int tt = T_LEN - 2; tt >= 0; --tt) {
            st = bp[tt * 64 + st];
            out[64 + (size_t)tt * B_SZ + b] = (float)st;
        }
    }
}

// =====================================================================
extern "C" void kernel_launch(void* const* d_in, const int* in_sizes, int n_in,
                              void* d_out, int out_size)
{
    const int*   obs  = (const int*)  d_in[0];
    const float* h0   = (const float*)d_in[1];
    const float* c0   = (const float*)d_in[2];
    const float* emb  = (const float*)d_in[3];
    const float* WihF = (const float*)d_in[4];
    const float* WhhF = (const float*)d_in[5];
    const float* bihF = (const float*)d_in[6];
    const float* bhhF = (const float*)d_in[7];
    const float* WihB = (const float*)d_in[8];
    const float* WhhB = (const float*)d_in[9];
    const float* bihB = (const float*)d_in[10];
    const float* bhhB = (const float*)d_in[11];
    const float* Wlin = (const float*)d_in[12];
    const float* blin = (const float*)d_in[13];
    const float* pw   = (const float*)d_in[14];
    const float* stv  = (const float*)d_in[15];
    const float* spv  = (const float*)d_in[16];
    float* out = (float*)d_out;

    const int smemB = (int)sizeof(SmemB);
    const int smemC = 4096 * 4 + 64 * 4 + 64 * 4 + (T_LEN - 1) * 64;

    cudaFuncSetAttribute(kB, cudaFuncAttributeMaxDynamicSharedMemorySize, smemB);
    cudaFuncSetAttribute(kC, cudaFuncAttributeMaxDynamicSharedMemorySize, smemC);

    kA<<<dim3(256, 32), 256>>>(obs, emb, WihF, WihB, bihF, bhhF, bihB, bhhB);
    kB<<<128, 256, smemB>>>(WhhF, WhhB, h0, c0, Wlin);
    kC<<<64, 64, smemC>>>(blin, pw, stv, spv, out);
}

// round 2
// speedup vs baseline: 1.2688x; 1.2688x over previous
#include <cuda_runtime.h>
#include <cuda_bf16.h>
#include <math.h>

typedef unsigned long long ull;

// ---------------- constants ----------------
#define T_LEN 512
#define B_SZ  64
#define E_DIM 256
#define H_DIM 256
#define S_ST  64
#define G4H   1024   // 4*H

// ---------------- device scratch ----------------
__device__ float g_xg[2][T_LEN][B_SZ][G4H];   // precomputed x-gates + bias (chain-step order)
__device__ float g_h[T_LEN * B_SZ][2 * H_DIM]; // BiLSTM features [t*B+b][dir*256+k]
__device__ float g_sc[T_LEN * B_SZ][S_ST];     // emission scores (incl b_lin)

// ---------------- f32x2 helpers ----------------
__device__ __forceinline__ ull pk2(float x, float y) {
    ull r; asm("mov.b64 %0, {%1,%2};" : "=l"(r) : "f"(x), "f"(y)); return r;
}
__device__ __forceinline__ void upk2(ull v, float& x, float& y) {
    asm("mov.b64 {%0,%1}, %2;" : "=f"(x), "=f"(y) : "l"(v));
}
__device__ __forceinline__ ull fma2_(ull a, ull b, ull c) {
    ull d; asm("fma.rn.f32x2 %0, %1, %2, %3;" : "=l"(d) : "l"(a), "l"(b), "l"(c)); return d;
}
__device__ __forceinline__ ull add2_(ull a, ull b) {
    ull d; asm("add.rn.f32x2 %0, %1, %2;" : "=l"(d) : "l"(a), "l"(b)); return d;
}
__device__ __forceinline__ unsigned smem_u32(const void* p) {
    unsigned a;
    asm("{ .reg .u64 t; cvta.to.shared.u64 t, %1; cvt.u32.u64 %0, t; }" : "=r"(a) : "l"(p));
    return a;
}
__device__ __forceinline__ unsigned mapa_(unsigned addr, unsigned rank) {
    unsigned r; asm("mapa.shared::cluster.u32 %0, %1, %2;" : "=r"(r) : "r"(addr), "r"(rank));
    return r;
}
#define CLUSTER_SYNC() do { \
    asm volatile("barrier.cluster.arrive.aligned;" ::: "memory"); \
    asm volatile("barrier.cluster.wait.aligned;"   ::: "memory"); \
} while (0)

__device__ __forceinline__ float sgm(float x) { return 1.0f / (1.0f + expf(-x)); }
__device__ __forceinline__ float tanh_(float x) { return 1.0f - 2.0f / (expf(2.0f * x) + 1.0f); }

// =====================================================================
// Kernel A: x-gates GEMM.
//   xg[dir][s][b][g] = emb[obs[t,b]] . Wih_dir[g,:] + bih[g]+bhh[g]
//   fwd: s = t ; bwd: s = 511 - t  (chain-step order)
// Tiles: BM=128, BN=64, BK=32. f32x2 micro 8x4 with M-paired lanes.
// =====================================================================
__global__ void __launch_bounds__(256) kA(
    const int* __restrict__ obs, const float* __restrict__ emb,
    const float* __restrict__ WihF, const float* __restrict__ WihB,
    const float* __restrict__ bihF, const float* __restrict__ bhhF,
    const float* __restrict__ bihB, const float* __restrict__ bhhB)
{
    __shared__ float As[32][132];
    __shared__ float Bs[32][68];
    __shared__ int rowidx[128];

    const int tid = threadIdx.x;
    const int mBase = blockIdx.x * 128;
    const int nTile = blockIdx.y;            // 0..31
    const int dir = nTile >> 4;
    const int nBase = (nTile & 15) * 64;
    const float* W = dir ? WihB : WihF;

    if (tid < 128) rowidx[tid] = obs[mBase + tid];
    __syncthreads();

    const int ty = tid >> 4;   // 0..15 row-groups of 8
    const int tx = tid & 15;   // 0..15 col-groups of 4

    ull acc[4][4];             // [row-pair m][col j], lanes = rows (2m,2m+1)
#pragma unroll
    for (int m = 0; m < 4; m++)
#pragma unroll
        for (int j = 0; j < 4; j++) acc[m][j] = 0ull;

    const int arow = tid >> 3, akq = tid & 7;
    const int bn = tid >> 2, bkq = tid & 3;

    for (int kt = 0; kt < 8; ++kt) {
#pragma unroll
        for (int rr = 0; rr < 4; ++rr) {
            int r = arow + rr * 32;
            const float4 v = *reinterpret_cast<const float4*>(
                &emb[(size_t)rowidx[r] * E_DIM + kt * 32 + akq * 4]);
            As[akq * 4 + 0][r] = v.x; As[akq * 4 + 1][r] = v.y;
            As[akq * 4 + 2][r] = v.z; As[akq * 4 + 3][r] = v.w;
        }
#pragma unroll
        for (int hh = 0; hh < 2; ++hh) {
            const float4 v = *reinterpret_cast<const float4*>(
                &W[(size_t)(nBase + bn) * E_DIM + kt * 32 + bkq * 8 + hh * 4]);
            Bs[bkq * 8 + hh * 4 + 0][bn] = v.x; Bs[bkq * 8 + hh * 4 + 1][bn] = v.y;
            Bs[bkq * 8 + hh * 4 + 2][bn] = v.z; Bs[bkq * 8 + hh * 4 + 3][bn] = v.w;
        }
        __syncthreads();
#pragma unroll 8
        for (int k = 0; k < 32; ++k) {
            float4 a0 = *reinterpret_cast<const float4*>(&As[k][ty * 8]);
            float4 a1 = *reinterpret_cast<const float4*>(&As[k][ty * 8 + 4]);
            float4 b4 = *reinterpret_cast<const float4*>(&Bs[k][tx * 4]);
            ull ap[4] = {pk2(a0.x, a0.y), pk2(a0.z, a0.w), pk2(a1.x, a1.y), pk2(a1.z, a1.w)};
            ull bd[4] = {pk2(b4.x, b4.x), pk2(b4.y, b4.y), pk2(b4.z, b4.z), pk2(b4.w, b4.w)};
#pragma unroll
            for (int m = 0; m < 4; ++m)
#pragma unroll
                for (int j = 0; j < 4; ++j)
                    acc[m][j] = fma2_(ap[m], bd[j], acc[m][j]);
        }
        __syncthreads();
    }

    // epilogue: +bias, scatter (fwd as-is, bwd time-reversed)
    const int n0 = nBase + tx * 4;
    const float* bi = dir ? bihB : bihF;
    const float* bh = dir ? bhhB : bhhF;
    float bias[4];
#pragma unroll
    for (int j = 0; j < 4; ++j) bias[j] = bi[n0 + j] + bh[n0 + j];
#pragma unroll
    for (int m = 0; m < 4; ++m) {
        float lo[4], hi[4];
#pragma unroll
        for (int j = 0; j < 4; ++j) upk2(acc[m][j], lo[j], hi[j]);
        int mg0 = mBase + ty * 8 + 2 * m;
#pragma unroll
        for (int r = 0; r < 2; ++r) {
            int mg = mg0 + r;
            int t = mg >> 6, b = mg & 63;
            int sIdx = dir ? (T_LEN - 1 - t) : t;
            const float* src = r ? hi : lo;
            float4 o = make_float4(src[0] + bias[0], src[1] + bias[1],
                                   src[2] + bias[2], src[3] + bias[3]);
            *reinterpret_cast<float4*>(&g_xg[dir][sIdx][b][n0]) = o;
        }
    }
}

// =====================================================================
// Kernel B: recurrence. 16 clusters of 8 CTAs (2 dirs x 8 batch-groups).
// Whh slice lives in REGISTERS (512 threads x 64 weights). Per step:
// GEMV (K split 8) -> smem reduce -> LSTM cell -> DSMEM h-exchange ->
// h store to gmem (scores computed later by kS).
// =====================================================================
struct SmemB {
    float hbuf[2][H_DIM][8];     // full h [k][batch], ping-pong  16384 B
    ull   gred[8 * 8 * 64];      // [slot][ksplit][rowpair]       32768 B
    float gfull[8][132];         // gates [batch][row(+pad)]       4224 B
    float hstage[256];           // new h slice [u*8+bb]           1024 B
};

__global__ void __launch_bounds__(512, 1) __cluster_dims__(8, 1, 1) kB(
    const float* __restrict__ WhhF, const float* __restrict__ WhhB,
    const float* __restrict__ h0, const float* __restrict__ c0)
{
    extern __shared__ char smraw[];
    SmemB& sm = *reinterpret_cast<SmemB*>(smraw);

    const int tid = threadIdx.x;
    const int blk = blockIdx.x;
    const int cr = blk & 7;            // cluster rank -> owns units [32cr,32cr+32)
    const int cid = blk >> 3;          // 0..15
    const int dir = cid >> 3;
    const int b0 = (cid & 7) * 8;
    const float* Whh = dir ? WhhB : WhhF;
    const float* xg = &g_xg[dir][0][0][0];

    // ---- GEMV role: ksplit c, row-pair rp ----
    const int c = tid >> 6;            // 0..7 (32-k chunk)
    const int rp = tid & 63;           // 0..63 (rows 2rp, 2rp+1)
    const int jA = 2 * rp, jB = 2 * rp + 1;
    const int rgA = ((jA >> 5) << 8) + (cr << 5) + (jA & 31);
    const int rgB = ((jB >> 5) << 8) + (cr << 5) + (jB & 31);

    // Whh slice into registers: 64 floats/thread
    float wA[32], wB[32];
    {
        const float4* pA = reinterpret_cast<const float4*>(&Whh[(size_t)rgA * H_DIM + 32 * c]);
        const float4* pB = reinterpret_cast<const float4*>(&Whh[(size_t)rgB * H_DIM + 32 * c]);
#pragma unroll
        for (int q = 0; q < 8; ++q) {
            float4 va = pA[q], vb = pB[q];
            wA[q * 4 + 0] = va.x; wA[q * 4 + 1] = va.y; wA[q * 4 + 2] = va.z; wA[q * 4 + 3] = va.w;
            wB[q * 4 + 0] = vb.x; wB[q * 4 + 1] = vb.y; wB[q * 4 + 2] = vb.z; wB[q * 4 + 3] = vb.w;
        }
    }

    // ---- output/reduce role: slot, rpo ----
    const int slot = tid >> 6;         // 0..7 = delta*4 + m
    const int rpo = tid & 63;
    const int jOut = 2 * rpo + (slot >> 2);
    const int mOut = slot & 3;         // batch pair (2m, 2m+1)
    const int rgOut = ((jOut >> 5) << 8) + (cr << 5) + (jOut & 31);
    const float* pXg0 = xg + ((size_t)(b0 + 2 * mOut)) * G4H + rgOut;
    const float* pXg1 = pXg0 + G4H;

    // ---- init hbuf[0] with h0 (full h per CTA) ----
    for (int idx = tid; idx < 2048; idx += 512) {
        int k = idx >> 3, bb = idx & 7;
        sm.hbuf[0][k][bb] = h0[((size_t)dir * B_SZ + b0 + bb) * H_DIM + k];
    }

    // ---- cell role: u, bb (tid < 256) ----
    const int u = tid >> 3, bb = tid & 7;
    float c_reg = 0.f;
    if (tid < 256)
        c_reg = c0[((size_t)dir * B_SZ + b0 + bb) * H_DIM + cr * 32 + u];

    // ---- exchange role ----
    const int xTg = (cr + (tid >> 6)) & 7;       // target rank (skewed)
    const int xChunk = tid & 63;                  // 16B chunk of hstage
    const unsigned xLocal = smem_u32(&sm.hbuf[0][cr * 32 + (xChunk >> 1)][(xChunk & 1) * 4]);
    const unsigned xRemoteBase = mapa_(xLocal, (unsigned)xTg);
    const unsigned hbufStride = (unsigned)(H_DIM * 8 * sizeof(float)); // hbuf[1]-hbuf[0]

    // ---- h gmem store role (tid < 64) ----
    const int sb = tid >> 3, skq = tid & 7;       // batch, k-quad

    __syncthreads();
    CLUSTER_SYNC();

    for (int s = 0; s < T_LEN; ++s) {
        const int p = s & 1, q = p ^ 1;

        // prefetch xg for output role
        const size_t sOff = (size_t)s * B_SZ * G4H;
        const float xv0 = pXg0[sOff];
        const float xv1 = pXg1[sOff];

        // ---- GEMV over 32-k chunk, weights in regs ----
        ull aA0 = 0, aA1 = 0, aA2 = 0, aA3 = 0;
        ull aB0 = 0, aB1 = 0, aB2 = 0, aB3 = 0;
        const ull* hp = reinterpret_cast<const ull*>(&sm.hbuf[p][32 * c][0]);
#pragma unroll
        for (int k = 0; k < 32; ++k) {
            ull h0v = hp[k * 4 + 0], h1v = hp[k * 4 + 1];
            ull h2v = hp[k * 4 + 2], h3v = hp[k * 4 + 3];
            ull wa = pk2(wA[k], wA[k]);
            ull wb = pk2(wB[k], wB[k]);
            aA0 = fma2_(wa, h0v, aA0); aA1 = fma2_(wa, h1v, aA1);
            aA2 = fma2_(wa, h2v, aA2); aA3 = fma2_(wa, h3v, aA3);
            aB0 = fma2_(wb, h0v, aB0); aB1 = fma2_(wb, h1v, aB1);
            aB2 = fma2_(wb, h2v, aB2); aB3 = fma2_(wb, h3v, aB3);
        }
        // store partials: gred[(slot*8 + c)*64 + rp]
        {
            ull* g = sm.gred;
            g[(0 * 8 + c) * 64 + rp] = aA0;
            g[(1 * 8 + c) * 64 + rp] = aA1;
            g[(2 * 8 + c) * 64 + rp] = aA2;
            g[(3 * 8 + c) * 64 + rp] = aA3;
            g[(4 * 8 + c) * 64 + rp] = aB0;
            g[(5 * 8 + c) * 64 + rp] = aB1;
            g[(6 * 8 + c) * 64 + rp] = aB2;
            g[(7 * 8 + c) * 64 + rp] = aB3;
        }
        __syncthreads();

        // ---- reduce over 8 k-chunks, add xg, write gates ----
        {
            const ull* g = &sm.gred[(size_t)slot * 8 * 64 + rpo];
            ull r0 = add2_(g[0], g[64]);
            ull r1 = add2_(g[128], g[192]);
            ull r2 = add2_(g[256], g[320]);
            ull r3 = add2_(g[384], g[448]);
            ull r = add2_(add2_(r0, r1), add2_(r2, r3));
            r = add2_(r, pk2(xv0, xv1));
            float lo, hi; upk2(r, lo, hi);
            sm.gfull[2 * mOut][jOut] = lo;
            sm.gfull[2 * mOut + 1][jOut] = hi;
        }
        __syncthreads();

        // ---- LSTM cell (tid < 256) ----
        if (tid < 256) {
            float gi = sm.gfull[bb][u];
            float gf = sm.gfull[bb][32 + u];
            float gg = sm.gfull[bb][64 + u];
            float go = sm.gfull[bb][96 + u];
            float cc = sgm(gf) * c_reg + sgm(gi) * tanh_(gg);
            c_reg = cc;
            sm.hstage[tid] = sgm(go) * tanh_(cc);
        }
        __syncthreads();

        // ---- DSMEM exchange: everyone pushes the owned slice everywhere ----
        {
            const float4 v = *reinterpret_cast<const float4*>(&sm.hstage[xChunk * 4]);
            unsigned ra = xRemoteBase + (unsigned)q * hbufStride;
            asm volatile("st.shared::cluster.v4.f32 [%0], {%1,%2,%3,%4};"
                         :: "r"(ra), "f"(v.x), "f"(v.y), "f"(v.z), "f"(v.w) : "memory");
        }
        // ---- h to gmem for score GEMM (tid < 64) ----
        if (tid < 64) {
            float4 o;
            o.x = sm.hstage[(skq * 4 + 0) * 8 + sb];
            o.y = sm.hstage[(skq * 4 + 1) * 8 + sb];
            o.z = sm.hstage[(skq * 4 + 2) * 8 + sb];
            o.w = sm.hstage[(skq * 4 + 3) * 8 + sb];
            int tOut = dir ? (T_LEN - 1 - s) : s;
            *reinterpret_cast<float4*>(
                &g_h[(size_t)tOut * B_SZ + b0 + sb][dir * H_DIM + cr * 32 + skq * 4]) = o;
        }
        CLUSTER_SYNC();
    }
}

// =====================================================================
// Kernel S: emission scores GEMM.  sc[t*B+b][s] = feats . W_lin[s] + b_lin
// BM=128, BN=64, BK=32, K=512.
// =====================================================================
__global__ void __launch_bounds__(256) kS(
    const float* __restrict__ Wlin, const float* __restrict__ blin)
{
    __shared__ float As[32][132];
    __shared__ float Bs[32][68];

    const int tid = threadIdx.x;
    const int mBase = blockIdx.x * 128;

    const int ty = tid >> 4;
    const int tx = tid & 15;

    ull acc[4][4];
#pragma unroll
    for (int m = 0; m < 4; m++)
#pragma unroll
        for (int j = 0; j < 4; j++) acc[m][j] = 0ull;

    const int arow = tid >> 3, akq = tid & 7;
    const int bn = tid >> 2, bkq = tid & 3;

    for (int kt = 0; kt < 16; ++kt) {
#pragma unroll
        for (int rr = 0; rr < 4; ++rr) {
            int r = arow + rr * 32;
            const float4 v = *reinterpret_cast<const float4*>(
                &g_h[mBase + r][kt * 32 + akq * 4]);
            As[akq * 4 + 0][r] = v.x; As[akq * 4 + 1][r] = v.y;
            As[akq * 4 + 2][r] = v.z; As[akq * 4 + 3][r] = v.w;
        }
#pragma unroll
        for (int hh = 0; hh < 2; ++hh) {
            const float4 v = *reinterpret_cast<const float4*>(
                &Wlin[(size_t)bn * (2 * H_DIM) + kt * 32 + bkq * 8 + hh * 4]);
            Bs[bkq * 8 + hh * 4 + 0][bn] = v.x; Bs[bkq * 8 + hh * 4 + 1][bn] = v.y;
            Bs[bkq * 8 + hh * 4 + 2][bn] = v.z; Bs[bkq * 8 + hh * 4 + 3][bn] = v.w;
        }
        __syncthreads();
#pragma unroll 8
        for (int k = 0; k < 32; ++k) {
            float4 a0 = *reinterpret_cast<const float4*>(&As[k][ty * 8]);
            float4 a1 = *reinterpret_cast<const float4*>(&As[k][ty * 8 + 4]);
            float4 b4 = *reinterpret_cast<const float4*>(&Bs[k][tx * 4]);
            ull ap[4] = {pk2(a0.x, a0.y), pk2(a0.z, a0.w), pk2(a1.x, a1.y), pk2(a1.z, a1.w)};
            ull bd[4] = {pk2(b4.x, b4.x), pk2(b4.y, b4.y), pk2(b4.z, b4.z), pk2(b4.w, b4.w)};
#pragma unroll
            for (int m = 0; m < 4; ++m)
#pragma unroll
                for (int j = 0; j < 4; ++j)
                    acc[m][j] = fma2_(ap[m], bd[j], acc[m][j]);
        }
        __syncthreads();
    }

    const int n0 = tx * 4;
    float bias[4];
#pragma unroll
    for (int j = 0; j < 4; ++j) bias[j] = blin[n0 + j];
#pragma unroll
    for (int m = 0; m < 4; ++m) {
        float lo[4], hi[4];
#pragma unroll
        for (int j = 0; j < 4; ++j) upk2(acc[m][j], lo[j], hi[j]);
        int row0 = mBase + ty * 8 + 2 * m;
#pragma unroll
        for (int r = 0; r < 2; ++r) {
            const float* src = r ? hi : lo;
            float4 o = make_float4(src[0] + bias[0], src[1] + bias[1],
                                   src[2] + bias[2], src[3] + bias[3]);
            *reinterpret_cast<float4*>(&g_sc[row0 + r][n0]) = o;
        }
    }
}

// =====================================================================
// Kernel C: Viterbi DP + backtrace. One CTA per batch, P in registers,
// bp kept in SMEM. 4 blocked argmax chains, exact first-max ties.
// =====================================================================
__global__ void __launch_bounds__(64) kC(
    const float* __restrict__ pw,
    const float* __restrict__ startv, const float* __restrict__ stopv,
    float* __restrict__ out)
{
    extern __shared__ char smc[];
    float* delta = reinterpret_cast<float*>(smc);            // 64
    float* fin = delta + 64;                                 // 64
    unsigned char* bp = reinterpret_cast<unsigned char*>(fin + 64); // 511*64

    const int b = blockIdx.x;
    const int tid = threadIdx.x;

    float P[64];
#pragma unroll
    for (int pv = 0; pv < 64; ++pv) P[pv] = pw[pv * 64 + tid];

    delta[tid] = startv[tid] + g_sc[(size_t)0 * B_SZ + b][tid];
    __syncthreads();

    float scN = g_sc[(size_t)1 * B_SZ + b][tid];
    for (int t = 1; t < T_LEN; ++t) {
        const float sc = scN;
        if (t < T_LEN - 1) scN = g_sc[(size_t)(t + 1) * B_SZ + b][tid];

        float bv[4] = {-3.0e38f, -3.0e38f, -3.0e38f, -3.0e38f};
        int bi[4] = {0, 16, 32, 48};
#pragma unroll
        for (int g = 0; g < 4; ++g) {
#pragma unroll
            for (int k = 0; k < 16; ++k) {
                int pv = g * 16 + k;
                float v = delta[pv] + P[pv];
                if (v > bv[g]) { bv[g] = v; bi[g] = pv; }
            }
        }
        float best = bv[0]; int bidx = bi[0];
        if (bv[1] > best) { best = bv[1]; bidx = bi[1]; }
        if (bv[2] > best) { best = bv[2]; bidx = bi[2]; }
        if (bv[3] > best) { best = bv[3]; bidx = bi[3]; }

        bp[(t - 1) * 64 + tid] = (unsigned char)bidx;
        __syncthreads();
        delta[tid] = best + sc;
        __syncthreads();
    }

    fin[tid] = delta[tid] + stopv[tid];
    __syncthreads();
    if (tid == 0) {
        float best = fin[0]; int bi0 = 0;
        for (int i = 1; i < 64; ++i) if (fin[i] > best) { best = fin[i]; bi0 = i; }
        out[b] = best;
        int st = bi0;
        out[64 + (size_t)(T_LEN - 1) * B_SZ + b] = (float)st;
        for (int tt = T_LEN - 2; tt >= 0; --tt) {
            st = bp[tt * 64 + st];
            out[64 + (size_t)tt * B_SZ + b] = (float)st;
        }
    }
}

// =====================================================================
extern "C" void kernel_launch(void* const* d_in, const int* in_sizes, int n_in,
                              void* d_out, int out_size)
{
    const int*   obs  = (const int*)  d_in[0];
    const float* h0   = (const float*)d_in[1];
    const float* c0   = (const float*)d_in[2];
    const float* emb  = (const float*)d_in[3];
    const float* WihF = (const float*)d_in[4];
    const float* WhhF = (const float*)d_in[5];
    const float* bihF = (const float*)d_in[6];
    const float* bhhF = (const float*)d_in[7];
    const float* WihB = (const float*)d_in[8];
    const float* WhhB = (const float*)d_in[9];
    const float* bihB = (const float*)d_in[10];
    const float* bhhB = (const float*)d_in[11];
    const float* Wlin = (const float*)d_in[12];
    const float* blin = (const float*)d_in[13];
    const float* pw   = (const float*)d_in[14];
    const float* stv  = (const float*)d_in[15];
    const float* spv  = (const float*)d_in[16];
    float* out = (float*)d_out;

    const int smemB = (int)sizeof(SmemB);
    const int smemC = 64 * 4 + 64 * 4 + (T_LEN - 1) * 64;

    cudaFuncSetAttribute(kB, cudaFuncAttributeMaxDynamicSharedMemorySize, smemB);
    cudaFuncSetAttribute(kC, cudaFuncAttributeMaxDynamicSharedMemorySize, smemC);

    kA<<<dim3(256, 32), 256>>>(obs, emb, WihF, WihB, bihF, bhhF, bihB, bhhB);
    kB<<<128, 512, smemB>>>(WhhF, WhhB, h0, c0);
    kS<<<256, 256>>>(Wlin, blin);
    kC<<<64, 64, smemC>>>(pw, stv, spv, out);
}

// round 4
// speedup vs baseline: 1.5430x; 1.2161x over previous
#include <cuda_runtime.h>
#include <cuda_bf16.h>
#include <math.h>

typedef unsigned long long ull;

// ---------------- constants ----------------
#define T_LEN 512
#define B_SZ  64
#define E_DIM 256
#define H_DIM 256
#define S_ST  64
#define G4H   1024   // 4*H

// ---------------- device scratch ----------------
__device__ float g_xg[2][T_LEN][B_SZ][G4H];   // precomputed x-gates + bias (chain-step order)
__device__ float g_h[T_LEN * B_SZ][2 * H_DIM]; // BiLSTM features [t*B+b][dir*256+k]
__device__ float g_sc[T_LEN * B_SZ][S_ST];     // emission scores (incl b_lin)

// ---------------- f32x2 helpers ----------------
__device__ __forceinline__ ull pk2(float x, float y) {
    ull r; asm("mov.b64 %0, {%1,%2};" : "=l"(r) : "f"(x), "f"(y)); return r;
}
__device__ __forceinline__ void upk2(ull v, float& x, float& y) {
    asm("mov.b64 {%0,%1}, %2;" : "=f"(x), "=f"(y) : "l"(v));
}
__device__ __forceinline__ ull fma2_(ull a, ull b, ull c) {
    ull d; asm("fma.rn.f32x2 %0, %1, %2, %3;" : "=l"(d) : "l"(a), "l"(b), "l"(c)); return d;
}
__device__ __forceinline__ ull add2_(ull a, ull b) {
    ull d; asm("add.rn.f32x2 %0, %1, %2;" : "=l"(d) : "l"(a), "l"(b)); return d;
}
__device__ __forceinline__ unsigned smem_u32(const void* p) {
    unsigned a;
    asm("{ .reg .u64 t; cvta.to.shared.u64 t, %1; cvt.u32.u64 %0, t; }" : "=r"(a) : "l"(p));
    return a;
}
__device__ __forceinline__ unsigned mapa_(unsigned addr, unsigned rank) {
    unsigned r; asm("mapa.shared::cluster.u32 %0, %1, %2;" : "=r"(r) : "r"(addr), "r"(rank));
    return r;
}
#define CLUSTER_SYNC() do { \
    asm volatile("barrier.cluster.arrive.aligned;" ::: "memory"); \
    asm volatile("barrier.cluster.wait.aligned;"   ::: "memory"); \
} while (0)

#define MBAR_INIT(addr, cnt) \
    asm volatile("mbarrier.init.shared.b64 [%0], %1;" :: "r"(addr), "r"(cnt) : "memory")

#define MBAR_INVAL(addr) \
    asm volatile("mbarrier.inval.shared.b64 [%0];" :: "r"(addr) : "memory")

#define MBAR_EXPECT_TX(addr, tx) \
    asm volatile("mbarrier.arrive.expect_tx.shared.b64 _, [%0], %1;" \
                 :: "r"(addr), "r"(tx) : "memory")

#define MBAR_ARRIVE_CLUSTER(raddr) \
    asm volatile("mbarrier.arrive.shared::cluster.b64 _, [%0];" :: "r"(raddr) : "memory")

#define MBAR_WAIT(addr, parity) do { \
    unsigned _mb = (addr); unsigned _ph = (parity); unsigned _done; \
    asm volatile("{\n\t.reg .pred p;\n\t" \
        "mbarrier.try_wait.parity.acquire.cta.shared::cta.b64 p, [%1], %2;\n\t" \
        "selp.b32 %0, 1, 0, p;\n\t}" : "=r"(_done) : "r"(_mb), "r"(_ph) : "memory"); \
    if (!_done) { \
        asm volatile("{\n\t.reg .pred P1;\n\t" \
            "WL_%=:\n\t" \
            "mbarrier.try_wait.parity.acquire.cta.shared::cta.b64 P1, [%0], %1, 0x989680;\n\t" \
            "@P1 bra.uni WD_%=;\n\t" \
            "bra.uni WL_%=;\n\t" \
            "WD_%=:\n\t}" :: "r"(_mb), "r"(_ph) : "memory"); \
    } \
} while (0)

#define BULK_S2S(dst, src, bytes, mbar) \
    asm volatile("cp.async.bulk.shared::cluster.shared::cta.mbarrier::complete_tx::bytes " \
                 "[%0], [%1], %2, [%3];" \
                 :: "r"(dst), "r"(src), "r"(bytes), "r"(mbar) : "memory")

__device__ __forceinline__ float sgm(float x) { return 1.0f / (1.0f + expf(-x)); }
__device__ __forceinline__ float tanh_(float x) { return 1.0f - 2.0f / (expf(2.0f * x) + 1.0f); }

// =====================================================================
// Kernel A: x-gates GEMM (unchanged).
// =====================================================================
__global__ void __launch_bounds__(256) kA(
    const int* __restrict__ obs, const float* __restrict__ emb,
    const float* __restrict__ WihF, const float* __restrict__ WihB,
    const float* __restrict__ bihF, const float* __restrict__ bhhF,
    const float* __restrict__ bihB, const float* __restrict__ bhhB)
{
    __shared__ float As[32][132];
    __shared__ float Bs[32][68];
    __shared__ int rowidx[128];

    const int tid = threadIdx.x;
    const int mBase = blockIdx.x * 128;
    const int nTile = blockIdx.y;
    const int dir = nTile >> 4;
    const int nBase = (nTile & 15) * 64;
    const float* W = dir ? WihB : WihF;

    if (tid < 128) rowidx[tid] = obs[mBase + tid];
    __syncthreads();

    const int ty = tid >> 4;
    const int tx = tid & 15;

    ull acc[4][4];
#pragma unroll
    for (int m = 0; m < 4; m++)
#pragma unroll
        for (int j = 0; j < 4; j++) acc[m][j] = 0ull;

    const int arow = tid >> 3, akq = tid & 7;
    const int bn = tid >> 2, bkq = tid & 3;

    for (int kt = 0; kt < 8; ++kt) {
#pragma unroll
        for (int rr = 0; rr < 4; ++rr) {
            int r = arow + rr * 32;
            const float4 v = *reinterpret_cast<const float4*>(
                &emb[(size_t)rowidx[r] * E_DIM + kt * 32 + akq * 4]);
            As[akq * 4 + 0][r] = v.x; As[akq * 4 + 1][r] = v.y;
            As[akq * 4 + 2][r] = v.z; As[akq * 4 + 3][r] = v.w;
        }
#pragma unroll
        for (int hh = 0; hh < 2; ++hh) {
            const float4 v = *reinterpret_cast<const float4*>(
                &W[(size_t)(nBase + bn) * E_DIM + kt * 32 + bkq * 8 + hh * 4]);
            Bs[bkq * 8 + hh * 4 + 0][bn] = v.x; Bs[bkq * 8 + hh * 4 + 1][bn] = v.y;
            Bs[bkq * 8 + hh * 4 + 2][bn] = v.z; Bs[bkq * 8 + hh * 4 + 3][bn] = v.w;
        }
        __syncthreads();
#pragma unroll 8
        for (int k = 0; k < 32; ++k) {
            float4 a0 = *reinterpret_cast<const float4*>(&As[k][ty * 8]);
            float4 a1 = *reinterpret_cast<const float4*>(&As[k][ty * 8 + 4]);
            float4 b4 = *reinterpret_cast<const float4*>(&Bs[k][tx * 4]);
            ull ap[4] = {pk2(a0.x, a0.y), pk2(a0.z, a0.w), pk2(a1.x, a1.y), pk2(a1.z, a1.w)};
            ull bd[4] = {pk2(b4.x, b4.x), pk2(b4.y, b4.y), pk2(b4.z, b4.z), pk2(b4.w, b4.w)};
#pragma unroll
            for (int m = 0; m < 4; ++m)
#pragma unroll
                for (int j = 0; j < 4; ++j)
                    acc[m][j] = fma2_(ap[m], bd[j], acc[m][j]);
        }
        __syncthreads();
    }

    const int n0 = nBase + tx * 4;
    const float* bi = dir ? bihB : bihF;
    const float* bh = dir ? bhhB : bhhF;
    float bias[4];
#pragma unroll
    for (int j = 0; j < 4; ++j) bias[j] = bi[n0 + j] + bh[n0 + j];
#pragma unroll
    for (int m = 0; m < 4; ++m) {
        float lo[4], hi[4];
#pragma unroll
        for (int j = 0; j < 4; ++j) upk2(acc[m][j], lo[j], hi[j]);
        int mg0 = mBase + ty * 8 + 2 * m;
#pragma unroll
        for (int r = 0; r < 2; ++r) {
            int mg = mg0 + r;
            int t = mg >> 6, b = mg & 63;
            int sIdx = dir ? (T_LEN - 1 - t) : t;
            const float* src = r ? hi : lo;
            float4 o = make_float4(src[0] + bias[0], src[1] + bias[1],
                                   src[2] + bias[2], src[3] + bias[3]);
            *reinterpret_cast<float4*>(&g_xg[dir][sIdx][b][n0]) = o;
        }
    }
}

// =====================================================================
// Kernel B: recurrence, mbarrier-pipelined DSMEM bulk h-exchange.
// FIXED vs R3: phF parity flips only after an actual wait (s>0);
// priming expect_tx before CLUSTER_SYNC; no pushes at the last step;
// barriers invalidated at exit (graph replay re-runs the kernel).
// =====================================================================
struct SmemB {
    float hbuf[2][H_DIM][8];     // full h [k][batch], ping-pong  16384 B
    ull   gred[8 * 8 * 64];      // [slot][ksplit][rowpair]       32768 B
    float gfull[8][132];         // gates [batch][row(+pad)]       4224 B
    float hstage[2][256];        // new h slice, double-buffered   2048 B
    ull   mb_full[2];            // data-arrival barriers (tx)
    ull   mb_go[2];              // back-pressure barriers (count 8)
};

__global__ void __launch_bounds__(512, 1) __cluster_dims__(8, 1, 1) kB(
    const float* __restrict__ WhhF, const float* __restrict__ WhhB,
    const float* __restrict__ h0, const float* __restrict__ c0)
{
    extern __shared__ char smraw[];
    SmemB& sm = *reinterpret_cast<SmemB*>(smraw);

    const int tid = threadIdx.x;
    const int blk = blockIdx.x;
    const int cr = blk & 7;            // cluster rank -> owns units [32cr,32cr+32)
    const int cid = blk >> 3;          // 0..15
    const int dir = cid >> 3;
    const int b0 = (cid & 7) * 8;
    const float* Whh = dir ? WhhB : WhhF;
    const float* xg = &g_xg[dir][0][0][0];

    // ---- GEMV role: ksplit c, row-pair rp ----
    const int c = tid >> 6;            // 0..7 (32-k chunk)
    const int rp = tid & 63;           // rows 2rp, 2rp+1
    const int jA = 2 * rp, jB = 2 * rp + 1;
    const int rgA = ((jA >> 5) << 8) + (cr << 5) + (jA & 31);
    const int rgB = ((jB >> 5) << 8) + (cr << 5) + (jB & 31);

    float wA[32], wB[32];
    {
        const float4* pA = reinterpret_cast<const float4*>(&Whh[(size_t)rgA * H_DIM + 32 * c]);
        const float4* pB = reinterpret_cast<const float4*>(&Whh[(size_t)rgB * H_DIM + 32 * c]);
#pragma unroll
        for (int qq = 0; qq < 8; ++qq) {
            float4 va = pA[qq], vb = pB[qq];
            wA[qq * 4 + 0] = va.x; wA[qq * 4 + 1] = va.y; wA[qq * 4 + 2] = va.z; wA[qq * 4 + 3] = va.w;
            wB[qq * 4 + 0] = vb.x; wB[qq * 4 + 1] = vb.y; wB[qq * 4 + 2] = vb.z; wB[qq * 4 + 3] = vb.w;
        }
    }

    // ---- output/reduce role ----
    const int slot = tid >> 6;
    const int rpo = tid & 63;
    const int jOut = 2 * rpo + (slot >> 2);
    const int mOut = slot & 3;
    const int rgOut = ((jOut >> 5) << 8) + (cr << 5) + (jOut & 31);
    const float* pXg0 = xg + ((size_t)(b0 + 2 * mOut)) * G4H + rgOut;
    const float* pXg1 = pXg0 + G4H;

    // ---- init hbuf[0] ----
    for (int idx = tid; idx < 2048; idx += 512) {
        int k = idx >> 3, bb = idx & 7;
        sm.hbuf[0][k][bb] = h0[((size_t)dir * B_SZ + b0 + bb) * H_DIM + k];
    }

    // ---- cell role ----
    const int u = tid >> 3, bb = tid & 7;
    float c_reg = 0.f;
    if (tid < 256)
        c_reg = c0[((size_t)dir * B_SZ + b0 + bb) * H_DIM + cr * 32 + u];

    // ---- messenger addresses (tid0) ----
    const unsigned goL0 = smem_u32(&sm.mb_go[0]);
    const unsigned goL1 = smem_u32(&sm.mb_go[1]);
    const unsigned fullL0 = smem_u32(&sm.mb_full[0]);
    const unsigned fullL1 = smem_u32(&sm.mb_full[1]);
    const unsigned dstL0 = smem_u32(&sm.hbuf[0][cr * 32][0]);
    const unsigned dstL1 = smem_u32(&sm.hbuf[1][cr * 32][0]);

    // ---- h gmem store role (tid < 64) ----
    const int sb = tid >> 3, skq = tid & 7;

    if (tid == 0) {
        MBAR_INIT(fullL0, 1); MBAR_INIT(fullL1, 1);
        MBAR_INIT(goL0, 8);   MBAR_INIT(goL1, 8);
        // arm full[1] for step-0 pushes BEFORE any peer can possibly push
        MBAR_EXPECT_TX(fullL1, 7168);
    }
    __syncthreads();
    CLUSTER_SYNC();

    // ---- prime: allow step-0 pushes into hbuf[1] ----
    if (tid == 0) {
#pragma unroll
        for (int j = 0; j < 8; ++j) MBAR_ARRIVE_CLUSTER(mapa_(goL1, (unsigned)j));
    }

    unsigned phF = 0;   // bit i = next wait parity for full[i]
    unsigned phG = 0;   // bit i = next wait parity for go[i] (tid0)

    for (int s = 0; s < T_LEN; ++s) {
        const int p = s & 1, q = p ^ 1;
        const unsigned fullLp = p ? fullL1 : fullL0;

        // ---- wait for h of this step (pushes from step s-1) ----
        if (s > 0) {
            MBAR_WAIT(fullLp, (phF >> p) & 1);
            phF ^= (1u << p);          // FIX: flip only when a phase was consumed
        }

        // prefetch xg for output role
        const size_t sOff = (size_t)s * B_SZ * G4H;
        const float xv0 = pXg0[sOff];
        const float xv1 = pXg1[sOff];

        // ---- GEMV over 32-k chunk, weights in regs, LDS.128 h ----
        ull aA0 = 0, aA1 = 0, aA2 = 0, aA3 = 0;
        ull aB0 = 0, aB1 = 0, aB2 = 0, aB3 = 0;
        const ulonglong2* hp2 = reinterpret_cast<const ulonglong2*>(&sm.hbuf[p][32 * c][0]);
#pragma unroll
        for (int k = 0; k < 32; ++k) {
            ulonglong2 hA = hp2[k * 2 + 0];
            ulonglong2 hB = hp2[k * 2 + 1];
            ull wa = pk2(wA[k], wA[k]);
            ull wb = pk2(wB[k], wB[k]);
            aA0 = fma2_(wa, hA.x, aA0); aA1 = fma2_(wa, hA.y, aA1);
            aA2 = fma2_(wa, hB.x, aA2); aA3 = fma2_(wa, hB.y, aA3);
            aB0 = fma2_(wb, hA.x, aB0); aB1 = fma2_(wb, hA.y, aB1);
            aB2 = fma2_(wb, hB.x, aB2); aB3 = fma2_(wb, hB.y, aB3);
        }
        {
            ull* g = sm.gred;
            g[(0 * 8 + c) * 64 + rp] = aA0;
            g[(1 * 8 + c) * 64 + rp] = aA1;
            g[(2 * 8 + c) * 64 + rp] = aA2;
            g[(3 * 8 + c) * 64 + rp] = aA3;
            g[(4 * 8 + c) * 64 + rp] = aB0;
            g[(5 * 8 + c) * 64 + rp] = aB1;
            g[(6 * 8 + c) * 64 + rp] = aB2;
            g[(7 * 8 + c) * 64 + rp] = aB3;
        }
        __syncthreads();   // all GEMV reads of hbuf[p] done

        // ---- messenger: my hbuf[p] is free; arm next incoming phase + open go ----
        if (tid == 0 && s < T_LEN - 1) {
            MBAR_EXPECT_TX(fullLp, 7168);   // step s+1 pushes target hbuf[p]
            const unsigned goLp = p ? goL1 : goL0;
#pragma unroll
            for (int j = 0; j < 8; ++j) MBAR_ARRIVE_CLUSTER(mapa_(goLp, (unsigned)j));
        }

        // ---- reduce over 8 k-chunks, add xg, write gates ----
        {
            const ull* g = &sm.gred[(size_t)slot * 8 * 64 + rpo];
            ull r0 = add2_(g[0], g[64]);
            ull r1 = add2_(g[128], g[192]);
            ull r2 = add2_(g[256], g[320]);
            ull r3 = add2_(g[384], g[448]);
            ull r = add2_(add2_(r0, r1), add2_(r2, r3));
            r = add2_(r, pk2(xv0, xv1));
            float lo, hi; upk2(r, lo, hi);
            sm.gfull[2 * mOut][jOut] = lo;
            sm.gfull[2 * mOut + 1][jOut] = hi;
        }
        __syncthreads();

        // ---- LSTM cell (tid < 256): write hstage + own slice of hbuf[q] ----
        if (tid < 256) {
            float gi = sm.gfull[bb][u];
            float gf = sm.gfull[bb][32 + u];
            float gg = sm.gfull[bb][64 + u];
            float go = sm.gfull[bb][96 + u];
            float cc = sgm(gf) * c_reg + sgm(gi) * tanh_(gg);
            c_reg = cc;
            float hv = sgm(go) * tanh_(cc);
            sm.hstage[p][tid] = hv;
            sm.hbuf[q][cr * 32 + u][bb] = hv;   // self-slice local
        }
        __syncthreads();

        // ---- tid0: push own slice to the 7 peers (skip at last step) ----
        if (tid == 0 && s < T_LEN - 1) {
            asm volatile("fence.proxy.async.shared::cta;" ::: "memory");
            const unsigned goLq = q ? goL1 : goL0;
            MBAR_WAIT(goLq, (phG >> q) & 1);
            phG ^= (1u << q);
            const unsigned src = smem_u32(&sm.hstage[p][0]);
            const unsigned dstLq = q ? dstL1 : dstL0;
            const unsigned fullLq = q ? fullL1 : fullL0;
#pragma unroll
            for (int j = 0; j < 8; ++j) {
                if (j == cr) continue;
                unsigned dst = mapa_(dstLq, (unsigned)j);
                unsigned mb = mapa_(fullLq, (unsigned)j);
                BULK_S2S(dst, src, 1024u, mb);
            }
        }

        // ---- h to gmem for score GEMM (tid < 64) ----
        if (tid < 64) {
            float4 o;
            o.x = sm.hstage[p][(skq * 4 + 0) * 8 + sb];
            o.y = sm.hstage[p][(skq * 4 + 1) * 8 + sb];
            o.z = sm.hstage[p][(skq * 4 + 2) * 8 + sb];
            o.w = sm.hstage[p][(skq * 4 + 3) * 8 + sb];
            int tOut = dir ? (T_LEN - 1 - s) : s;
            *reinterpret_cast<float4*>(
                &g_h[(size_t)tOut * B_SZ + b0 + sb][dir * H_DIM + cr * 32 + skq * 4]) = o;
        }
    }

    // all bulk ops of step T-2 were consumed at step T-1; none in flight now
    CLUSTER_SYNC();
    if (tid == 0) {
        MBAR_INVAL(fullL0); MBAR_INVAL(fullL1);
        MBAR_INVAL(goL0);   MBAR_INVAL(goL1);
    }
}

// =====================================================================
// Kernel S: emission scores GEMM (unchanged).
// =====================================================================
__global__ void __launch_bounds__(256) kS(
    const float* __restrict__ Wlin, const float* __restrict__ blin)
{
    __shared__ float As[32][132];
    __shared__ float Bs[32][68];

    const int tid = threadIdx.x;
    const int mBase = blockIdx.x * 128;

    const int ty = tid >> 4;
    const int tx = tid & 15;

    ull acc[4][4];
#pragma unroll
    for (int m = 0; m < 4; m++)
#pragma unroll
        for (int j = 0; j < 4; j++) acc[m][j] = 0ull;

    const int arow = tid >> 3, akq = tid & 7;
    const int bn = tid >> 2, bkq = tid & 3;

    for (int kt = 0; kt < 16; ++kt) {
#pragma unroll
        for (int rr = 0; rr < 4; ++rr) {
            int r = arow + rr * 32;
            const float4 v = *reinterpret_cast<const float4*>(
                &g_h[mBase + r][kt * 32 + akq * 4]);
            As[akq * 4 + 0][r] = v.x; As[akq * 4 + 1][r] = v.y;
            As[akq * 4 + 2][r] = v.z; As[akq * 4 + 3][r] = v.w;
        }
#pragma unroll
        for (int hh = 0; hh < 2; ++hh) {
            const float4 v = *reinterpret_cast<const float4*>(
                &Wlin[(size_t)bn * (2 * H_DIM) + kt * 32 + bkq * 8 + hh * 4]);
            Bs[bkq * 8 + hh * 4 + 0][bn] = v.x; Bs[bkq * 8 + hh * 4 + 1][bn] = v.y;
            Bs[bkq * 8 + hh * 4 + 2][bn] = v.z; Bs[bkq * 8 + hh * 4 + 3][bn] = v.w;
        }
        __syncthreads();
#pragma unroll 8
        for (int k = 0; k < 32; ++k) {
            float4 a0 = *reinterpret_cast<const float4*>(&As[k][ty * 8]);
            float4 a1 = *reinterpret_cast<const float4*>(&As[k][ty * 8 + 4]);
            float4 b4 = *reinterpret_cast<const float4*>(&Bs[k][tx * 4]);
            ull ap[4] = {pk2(a0.x, a0.y), pk2(a0.z, a0.w), pk2(a1.x, a1.y), pk2(a1.z, a1.w)};
            ull bd[4] = {pk2(b4.x, b4.x), pk2(b4.y, b4.y), pk2(b4.z, b4.z), pk2(b4.w, b4.w)};
#pragma unroll
            for (int m = 0; m < 4; ++m)
#pragma unroll
                for (int j = 0; j < 4; ++j)
                    acc[m][j] = fma2_(ap[m], bd[j], acc[m][j]);
        }
        __syncthreads();
    }

    const int n0 = tx * 4;
    float bias[4];
#pragma unroll
    for (int j = 0; j < 4; ++j) bias[j] = blin[n0 + j];
#pragma unroll
    for (int m = 0; m < 4; ++m) {
        float lo[4], hi[4];
#pragma unroll
        for (int j = 0; j < 4; ++j) upk2(acc[m][j], lo[j], hi[j]);
        int row0 = mBase + ty * 8 + 2 * m;
#pragma unroll
        for (int r = 0; r < 2; ++r) {
            const float* src = r ? hi : lo;
            float4 o = make_float4(src[0] + bias[0], src[1] + bias[1],
                                   src[2] + bias[2], src[3] + bias[3]);
            *reinterpret_cast<float4*>(&g_sc[row0 + r][n0]) = o;
        }
    }
}

// =====================================================================
// Kernel C: Viterbi DP + backtrace. One CTA/batch, 512 threads:
// 64 states x 8 lanes (8 prev-states each), shfl-bfly exact first-max
// merge, double-buffered delta, ONE barrier per step.
// =====================================================================
__global__ void __launch_bounds__(512) kC(
    const float* __restrict__ pw,
    const float* __restrict__ startv, const float* __restrict__ stopv,
    float* __restrict__ out)
{
    __shared__ float delta[2][64];
    __shared__ float fin[64];
    __shared__ unsigned char bp[T_LEN - 1][64];

    const int b = blockIdx.x;
    const int tid = threadIdx.x;
    const int s = tid >> 3;      // state 0..63
    const int p = tid & 7;       // part 0..7 (prev states p*8..p*8+7)

    float Pr[8];
#pragma unroll
    for (int i = 0; i < 8; ++i) Pr[i] = pw[(p * 8 + i) * 64 + s];

    if (p == 0) delta[0][s] = startv[s] + g_sc[b][s];
    __syncthreads();

    float scN = g_sc[(size_t)1 * B_SZ + b][s];
    for (int t = 1; t < T_LEN; ++t) {
        const int pp = (t - 1) & 1, qq = t & 1;
        float4 d0 = *reinterpret_cast<const float4*>(&delta[pp][p * 8]);
        float4 d1 = *reinterpret_cast<const float4*>(&delta[pp][p * 8 + 4]);
        float dv[8] = {d0.x, d0.y, d0.z, d0.w, d1.x, d1.y, d1.z, d1.w};

        float best = dv[0] + Pr[0];
        int bi = p * 8;
#pragma unroll
        for (int i = 1; i < 8; ++i) {
            float v = dv[i] + Pr[i];
            if (v > best) { best = v; bi = p * 8 + i; }
        }
        // exact first-max merge over the 8 parts
#pragma unroll
        for (int off = 1; off < 8; off <<= 1) {
            float ov = __shfl_xor_sync(0xffffffffu, best, off);
            int oi = __shfl_xor_sync(0xffffffffu, bi, off);
            if (ov > best || (ov == best && oi < bi)) { best = ov; bi = oi; }
        }

        const float sc = scN;
        if (t < T_LEN - 1) scN = g_sc[(size_t)(t + 1) * B_SZ + b][s];

        if (p == 0) {
            bp[t - 1][s] = (unsigned char)bi;
            delta[qq][s] = best + sc;
        }
        __syncthreads();
    }

    if (p == 0) fin[s] = delta[(T_LEN - 1) & 1][s] + stopv[s];
    __syncthreads();

    if (tid == 0) {
        float best = fin[0]; int bi0 = 0;
        for (int i = 1; i < 64; ++i) if (fin[i] > best) { best = fin[i]; bi0 = i; }
        out[b] = best;
        int st = bi0;
        out[64 + (size_t)(T_LEN - 1) * B_SZ + b] = (float)st;
        for (int tt = T_LEN - 2; tt >= 0; --tt) {
            st = bp[tt][st];
            out[64 + (size_t)tt * B_SZ + b] = (float)st;
        }
    }
}

// =====================================================================
extern "C" void kernel_launch(void* const* d_in, const int* in_sizes, int n_in,
                              void* d_out, int out_size)
{
    const int*   obs  = (const int*)  d_in[0];
    const float* h0   = (const float*)d_in[1];
    const float* c0   = (const float*)d_in[2];
    const float* emb  = (const float*)d_in[3];
    const float* WihF = (const float*)d_in[4];
    const float* WhhF = (const float*)d_in[5];
    const float* bihF = (const float*)d_in[6];
    const float* bhhF = (const float*)d_in[7];
    const float* WihB = (const float*)d_in[8];
    const float* WhhB = (const float*)d_in[9];
    const float* bihB = (const float*)d_in[10];
    const float* bhhB = (const float*)d_in[11];
    const float* Wlin = (const float*)d_in[12];
    const float* blin = (const float*)d_in[13];
    const float* pw   = (const float*)d_in[14];
    const float* stv  = (const float*)d_in[15];
    const float* spv  = (const float*)d_in[16];
    float* out = (float*)d_out;

    const int smemB = (int)sizeof(SmemB);
    cudaFuncSetAttribute(kB, cudaFuncAttributeMaxDynamicSharedMemorySize, smemB);

    kA<<<dim3(256, 32), 256>>>(obs, emb, WihF, WihB, bihF, bhhF, bihB, bhhB);
    kB<<<128, 512, smemB>>>(WhhF, WhhB, h0, c0);
    kS<<<256, 256>>>(Wlin, blin);
    kC<<<64, 512>>>(pw, stv, spv, out);
}

// round 5
// speedup vs baseline: 1.6770x; 1.0868x over previous
#include <cuda_runtime.h>
#include <cuda_bf16.h>
#include <math.h>

typedef unsigned long long ull;

// ---------------- constants ----------------
#define T_LEN 512
#define B_SZ  64
#define E_DIM 256
#define H_DIM 256
#define S_ST  64
#define G4H   1024   // 4*H

// ---------------- device scratch ----------------
__device__ float g_xg[2][T_LEN][B_SZ][G4H];   // precomputed x-gates + bias (chain-step order)
__device__ float g_h[T_LEN * B_SZ][2 * H_DIM]; // BiLSTM features [t*B+b][dir*256+k]
__device__ float g_sc[T_LEN * B_SZ][S_ST];     // emission scores (incl b_lin)

// ---------------- f32x2 helpers ----------------
__device__ __forceinline__ ull pk2(float x, float y) {
    ull r; asm("mov.b64 %0, {%1,%2};" : "=l"(r) : "f"(x), "f"(y)); return r;
}
__device__ __forceinline__ void upk2(ull v, float& x, float& y) {
    asm("mov.b64 {%0,%1}, %2;" : "=f"(x), "=f"(y) : "l"(v));
}
__device__ __forceinline__ ull fma2_(ull a, ull b, ull c) {
    ull d; asm("fma.rn.f32x2 %0, %1, %2, %3;" : "=l"(d) : "l"(a), "l"(b), "l"(c)); return d;
}
__device__ __forceinline__ ull add2_(ull a, ull b) {
    ull d; asm("add.rn.f32x2 %0, %1, %2;" : "=l"(d) : "l"(a), "l"(b)); return d;
}
__device__ __forceinline__ unsigned smem_u32(const void* p) {
    unsigned a;
    asm("{ .reg .u64 t; cvta.to.shared.u64 t, %1; cvt.u32.u64 %0, t; }" : "=r"(a) : "l"(p));
    return a;
}
__device__ __forceinline__ unsigned mapa_(unsigned addr, unsigned rank) {
    unsigned r; asm("mapa.shared::cluster.u32 %0, %1, %2;" : "=r"(r) : "r"(addr), "r"(rank));
    return r;
}
#define CLUSTER_SYNC() do { \
    asm volatile("barrier.cluster.arrive.aligned;" ::: "memory"); \
    asm volatile("barrier.cluster.wait.aligned;"   ::: "memory"); \
} while (0)

#define MBAR_INIT(addr, cnt) \
    asm volatile("mbarrier.init.shared.b64 [%0], %1;" :: "r"(addr), "r"(cnt) : "memory")

#define MBAR_INVAL(addr) \
    asm volatile("mbarrier.inval.shared.b64 [%0];" :: "r"(addr) : "memory")

#define MBAR_EXPECT_TX(addr, tx) \
    asm volatile("mbarrier.arrive.expect_tx.shared.b64 _, [%0], %1;" \
                 :: "r"(addr), "r"(tx) : "memory")

#define MBAR_ARRIVE_CLUSTER(raddr) \
    asm volatile("mbarrier.arrive.shared::cluster.b64 _, [%0];" :: "r"(raddr) : "memory")

#define MBAR_WAIT(addr, parity) do { \
    unsigned _mb = (addr); unsigned _ph = (parity); unsigned _done; \
    asm volatile("{\n\t.reg .pred p;\n\t" \
        "mbarrier.try_wait.parity.acquire.cta.shared::cta.b64 p, [%1], %2;\n\t" \
        "selp.b32 %0, 1, 0, p;\n\t}" : "=r"(_done) : "r"(_mb), "r"(_ph) : "memory"); \
    if (!_done) { \
        asm volatile("{\n\t.reg .pred P1;\n\t" \
            "WL_%=:\n\t" \
            "mbarrier.try_wait.parity.acquire.cta.shared::cta.b64 P1, [%0], %1, 0x989680;\n\t" \
            "@P1 bra.uni WD_%=;\n\t" \
            "bra.uni WL_%=;\n\t" \
            "WD_%=:\n\t}" :: "r"(_mb), "r"(_ph) : "memory"); \
    } \
} while (0)

#define BULK_S2S(dst, src, bytes, mbar) \
    asm volatile("cp.async.bulk.shared::cluster.shared::cta.mbarrier::complete_tx::bytes " \
                 "[%0], [%1], %2, [%3];" \
                 :: "r"(dst), "r"(src), "r"(bytes), "r"(mbar) : "memory")

__device__ __forceinline__ float sgm(float x) { return 1.0f / (1.0f + expf(-x)); }
__device__ __forceinline__ float tanh_(float x) { return 1.0f - 2.0f / (expf(2.0f * x) + 1.0f); }

// =====================================================================
// Kernel A: x-gates GEMM (unchanged).
// =====================================================================
__global__ void __launch_bounds__(256) kA(
    const int* __restrict__ obs, const float* __restrict__ emb,
    const float* __restrict__ WihF, const float* __restrict__ WihB,
    const float* __restrict__ bihF, const float* __restrict__ bhhF,
    const float* __restrict__ bihB, const float* __restrict__ bhhB)
{
    __shared__ float As[32][132];
    __shared__ float Bs[32][68];
    __shared__ int rowidx[128];

    const int tid = threadIdx.x;
    const int mBase = blockIdx.x * 128;
    const int nTile = blockIdx.y;
    const int dir = nTile >> 4;
    const int nBase = (nTile & 15) * 64;
    const float* W = dir ? WihB : WihF;

    if (tid < 128) rowidx[tid] = obs[mBase + tid];
    __syncthreads();

    const int ty = tid >> 4;
    const int tx = tid & 15;

    ull acc[4][4];
#pragma unroll
    for (int m = 0; m < 4; m++)
#pragma unroll
        for (int j = 0; j < 4; j++) acc[m][j] = 0ull;

    const int arow = tid >> 3, akq = tid & 7;
    const int bn = tid >> 2, bkq = tid & 3;

    for (int kt = 0; kt < 8; ++kt) {
#pragma unroll
        for (int rr = 0; rr < 4; ++rr) {
            int r = arow + rr * 32;
            const float4 v = *reinterpret_cast<const float4*>(
                &emb[(size_t)rowidx[r] * E_DIM + kt * 32 + akq * 4]);
            As[akq * 4 + 0][r] = v.x; As[akq * 4 + 1][r] = v.y;
            As[akq * 4 + 2][r] = v.z; As[akq * 4 + 3][r] = v.w;
        }
#pragma unroll
        for (int hh = 0; hh < 2; ++hh) {
            const float4 v = *reinterpret_cast<const float4*>(
                &W[(size_t)(nBase + bn) * E_DIM + kt * 32 + bkq * 8 + hh * 4]);
            Bs[bkq * 8 + hh * 4 + 0][bn] = v.x; Bs[bkq * 8 + hh * 4 + 1][bn] = v.y;
            Bs[bkq * 8 + hh * 4 + 2][bn] = v.z; Bs[bkq * 8 + hh * 4 + 3][bn] = v.w;
        }
        __syncthreads();
#pragma unroll 8
        for (int k = 0; k < 32; ++k) {
            float4 a0 = *reinterpret_cast<const float4*>(&As[k][ty * 8]);
            float4 a1 = *reinterpret_cast<const float4*>(&As[k][ty * 8 + 4]);
            float4 b4 = *reinterpret_cast<const float4*>(&Bs[k][tx * 4]);
            ull ap[4] = {pk2(a0.x, a0.y), pk2(a0.z, a0.w), pk2(a1.x, a1.y), pk2(a1.z, a1.w)};
            ull bd[4] = {pk2(b4.x, b4.x), pk2(b4.y, b4.y), pk2(b4.z, b4.z), pk2(b4.w, b4.w)};
#pragma unroll
            for (int m = 0; m < 4; ++m)
#pragma unroll
                for (int j = 0; j < 4; ++j)
                    acc[m][j] = fma2_(ap[m], bd[j], acc[m][j]);
        }
        __syncthreads();
    }

    const int n0 = nBase + tx * 4;
    const float* bi = dir ? bihB : bihF;
    const float* bh = dir ? bhhB : bhhF;
    float bias[4];
#pragma unroll
    for (int j = 0; j < 4; ++j) bias[j] = bi[n0 + j] + bh[n0 + j];
#pragma unroll
    for (int m = 0; m < 4; ++m) {
        float lo[4], hi[4];
#pragma unroll
        for (int j = 0; j < 4; ++j) upk2(acc[m][j], lo[j], hi[j]);
        int mg0 = mBase + ty * 8 + 2 * m;
#pragma unroll
        for (int r = 0; r < 2; ++r) {
            int mg = mg0 + r;
            int t = mg >> 6, b = mg & 63;
            int sIdx = dir ? (T_LEN - 1 - t) : t;
            const float* src = r ? hi : lo;
            float4 o = make_float4(src[0] + bias[0], src[1] + bias[1],
                                   src[2] + bias[2], src[3] + bias[3]);
            *reinterpret_cast<float4*>(&g_xg[dir][sIdx][b][n0]) = o;
        }
    }
}

// =====================================================================
// Kernel B: recurrence, TWO interleaved batch-group chains per CTA
// (same dir -> same Whh registers). Chain A's DSMEM comm is hidden
// behind chain B's compute and vice versa.
// 8 clusters of 8 CTAs: cluster = (dir, bgPair); CTA = unit slice.
// =====================================================================
struct SmemB {
    float hbuf[2][2][H_DIM][8];  // [chain][pingpong][k][batch]   32768 B
    ull   gred[8 * 8 * 64];      // [slot][ksplit][rowpair]       32768 B
    float gfull[8][132];         // gates [batch][row(+pad)]       4224 B
    float hstage[2][2][256];     // [chain][pingpong]              4096 B
    ull   mb_full[2][2];         // [chain][pingpong]
    ull   mb_go[2][2];           // [chain][pingpong] (count 8)
};

__global__ void __launch_bounds__(512, 1) __cluster_dims__(8, 1, 1) kB(
    const float* __restrict__ WhhF, const float* __restrict__ WhhB,
    const float* __restrict__ h0, const float* __restrict__ c0)
{
    extern __shared__ char smraw[];
    SmemB& sm = *reinterpret_cast<SmemB*>(smraw);

    const int tid = threadIdx.x;
    const int blk = blockIdx.x;
    const int cr = blk & 7;            // cluster rank -> owns units [32cr,32cr+32)
    const int cid = blk >> 3;          // 0..7
    const int dir = cid >> 2;          // 0 fwd, 1 bwd
    const int bgp = cid & 3;           // batch-group pair
    const int b0[2] = { bgp * 16, bgp * 16 + 8 };
    const float* Whh = dir ? WhhB : WhhF;
    const float* xg = &g_xg[dir][0][0][0];

    // ---- GEMV role: ksplit c, row-pair rp ----
    const int c = tid >> 6;            // 0..7 (32-k chunk)
    const int rp = tid & 63;           // rows 2rp, 2rp+1
    const int jA = 2 * rp, jB = 2 * rp + 1;
    const int rgA = ((jA >> 5) << 8) + (cr << 5) + (jA & 31);
    const int rgB = ((jB >> 5) << 8) + (cr << 5) + (jB & 31);

    float wA[32], wB[32];
    {
        const float4* pA = reinterpret_cast<const float4*>(&Whh[(size_t)rgA * H_DIM + 32 * c]);
        const float4* pB = reinterpret_cast<const float4*>(&Whh[(size_t)rgB * H_DIM + 32 * c]);
#pragma unroll
        for (int qq = 0; qq < 8; ++qq) {
            float4 va = pA[qq], vb = pB[qq];
            wA[qq * 4 + 0] = va.x; wA[qq * 4 + 1] = va.y; wA[qq * 4 + 2] = va.z; wA[qq * 4 + 3] = va.w;
            wB[qq * 4 + 0] = vb.x; wB[qq * 4 + 1] = vb.y; wB[qq * 4 + 2] = vb.z; wB[qq * 4 + 3] = vb.w;
        }
    }

    // ---- output/reduce role ----
    const int slot = tid >> 6;
    const int rpo = tid & 63;
    const int jOut = 2 * rpo + (slot >> 2);
    const int mOut = slot & 3;
    const int rgOut = ((jOut >> 5) << 8) + (cr << 5) + (jOut & 31);
    const float* pXg0[2] = {
        xg + ((size_t)(b0[0] + 2 * mOut)) * G4H + rgOut,
        xg + ((size_t)(b0[1] + 2 * mOut)) * G4H + rgOut };

    // ---- init hbuf[ch][0] with h0 ----
    for (int idx = tid; idx < 4096; idx += 512) {
        int ch = idx >> 11, r2 = idx & 2047;
        int k = r2 >> 3, bb = r2 & 7;
        sm.hbuf[ch][0][k][bb] = h0[((size_t)dir * B_SZ + b0[ch] + bb) * H_DIM + k];
    }

    // ---- cell role ----
    const int u = tid >> 3, bb = tid & 7;
    float c_reg[2] = {0.f, 0.f};
    if (tid < 256) {
        c_reg[0] = c0[((size_t)dir * B_SZ + b0[0] + bb) * H_DIM + cr * 32 + u];
        c_reg[1] = c0[((size_t)dir * B_SZ + b0[1] + bb) * H_DIM + cr * 32 + u];
    }

    // ---- messenger addresses (tid0) ----
    unsigned goL[2][2], fullL[2][2], dstL[2][2];
#pragma unroll
    for (int ch = 0; ch < 2; ++ch)
#pragma unroll
        for (int pp = 0; pp < 2; ++pp) {
            goL[ch][pp]   = smem_u32(&sm.mb_go[ch][pp]);
            fullL[ch][pp] = smem_u32(&sm.mb_full[ch][pp]);
            dstL[ch][pp]  = smem_u32(&sm.hbuf[ch][pp][cr * 32][0]);
        }

    // ---- h gmem store role (tid < 64) ----
    const int sb = tid >> 3, skq = tid & 7;

    if (tid == 0) {
#pragma unroll
        for (int ch = 0; ch < 2; ++ch) {
            MBAR_INIT(fullL[ch][0], 1); MBAR_INIT(fullL[ch][1], 1);
            MBAR_INIT(goL[ch][0], 8);   MBAR_INIT(goL[ch][1], 8);
            MBAR_EXPECT_TX(fullL[ch][1], 7168);   // arm for step-0 pushes
        }
    }
    __syncthreads();
    CLUSTER_SYNC();

    // ---- prime: open go[ch][1] everywhere ----
    if (tid == 0) {
#pragma unroll
        for (int ch = 0; ch < 2; ++ch)
#pragma unroll
            for (int j = 0; j < 8; ++j)
                MBAR_ARRIVE_CLUSTER(mapa_(goL[ch][1], (unsigned)j));
    }

    unsigned phF[2] = {0, 0};   // bit pp = next wait parity for full[ch][pp]
    unsigned phG[2] = {0, 0};   // bit pp = next wait parity for go[ch][pp] (tid0)

    for (int s = 0; s < T_LEN; ++s) {
        const int p = s & 1, q = p ^ 1;

#pragma unroll
        for (int ch = 0; ch < 2; ++ch) {
            const unsigned fullLp = fullL[ch][p];

            // ---- wait for this chain's h (pushes from step s-1) ----
            if (s > 0) {
                MBAR_WAIT(fullLp, (phF[ch] >> p) & 1);
                phF[ch] ^= (1u << p);
            }

            // prefetch xg for output role
            const size_t sOff = (size_t)s * B_SZ * G4H;
            const float xv0 = pXg0[ch][sOff];
            const float xv1 = pXg0[ch][sOff + G4H];

            // ---- GEMV over 32-k chunk, weights in regs ----
            ull aA0 = 0, aA1 = 0, aA2 = 0, aA3 = 0;
            ull aB0 = 0, aB1 = 0, aB2 = 0, aB3 = 0;
            const ulonglong2* hp2 =
                reinterpret_cast<const ulonglong2*>(&sm.hbuf[ch][p][32 * c][0]);
#pragma unroll
            for (int k = 0; k < 32; ++k) {
                ulonglong2 hA = hp2[k * 2 + 0];
                ulonglong2 hB = hp2[k * 2 + 1];
                ull wa = pk2(wA[k], wA[k]);
                ull wb = pk2(wB[k], wB[k]);
                aA0 = fma2_(wa, hA.x, aA0); aA1 = fma2_(wa, hA.y, aA1);
                aA2 = fma2_(wa, hB.x, aA2); aA3 = fma2_(wa, hB.y, aA3);
                aB0 = fma2_(wb, hA.x, aB0); aB1 = fma2_(wb, hA.y, aB1);
                aB2 = fma2_(wb, hB.x, aB2); aB3 = fma2_(wb, hB.y, aB3);
            }
            {
                ull* g = sm.gred;
                g[(0 * 8 + c) * 64 + rp] = aA0;
                g[(1 * 8 + c) * 64 + rp] = aA1;
                g[(2 * 8 + c) * 64 + rp] = aA2;
                g[(3 * 8 + c) * 64 + rp] = aA3;
                g[(4 * 8 + c) * 64 + rp] = aB0;
                g[(5 * 8 + c) * 64 + rp] = aB1;
                g[(6 * 8 + c) * 64 + rp] = aB2;
                g[(7 * 8 + c) * 64 + rp] = aB3;
            }
            __syncthreads();   // all GEMV reads of hbuf[ch][p] done

            // ---- messenger: hbuf[ch][p] free; arm next incoming phase + open go ----
            if (tid == 0 && s < T_LEN - 1) {
                MBAR_EXPECT_TX(fullLp, 7168);
#pragma unroll
                for (int j = 0; j < 8; ++j)
                    MBAR_ARRIVE_CLUSTER(mapa_(goL[ch][p], (unsigned)j));
            }

            // ---- reduce over 8 k-chunks, add xg, write gates ----
            {
                const ull* g = &sm.gred[(size_t)slot * 8 * 64 + rpo];
                ull r0 = add2_(g[0], g[64]);
                ull r1 = add2_(g[128], g[192]);
                ull r2 = add2_(g[256], g[320]);
                ull r3 = add2_(g[384], g[448]);
                ull r = add2_(add2_(r0, r1), add2_(r2, r3));
                r = add2_(r, pk2(xv0, xv1));
                float lo, hi; upk2(r, lo, hi);
                sm.gfull[2 * mOut][jOut] = lo;
                sm.gfull[2 * mOut + 1][jOut] = hi;
            }
            __syncthreads();

            // ---- LSTM cell (tid < 256) ----
            if (tid < 256) {
                float gi = sm.gfull[bb][u];
                float gf = sm.gfull[bb][32 + u];
                float gg = sm.gfull[bb][64 + u];
                float go = sm.gfull[bb][96 + u];
                float cc = sgm(gf) * c_reg[ch] + sgm(gi) * tanh_(gg);
                c_reg[ch] = cc;
                float hv = sgm(go) * tanh_(cc);
                sm.hstage[ch][p][tid] = hv;
                sm.hbuf[ch][q][cr * 32 + u][bb] = hv;   // self-slice local
            }
            __syncthreads();

            // ---- tid0: async push own slice to 7 peers (hidden by other chain) ----
            if (tid == 0 && s < T_LEN - 1) {
                asm volatile("fence.proxy.async.shared::cta;" ::: "memory");
                MBAR_WAIT(goL[ch][q], (phG[ch] >> q) & 1);
                phG[ch] ^= (1u << q);
                const unsigned src = smem_u32(&sm.hstage[ch][p][0]);
#pragma unroll
                for (int j = 0; j < 8; ++j) {
                    if (j == cr) continue;
                    unsigned dst = mapa_(dstL[ch][q], (unsigned)j);
                    unsigned mb = mapa_(fullL[ch][q], (unsigned)j);
                    BULK_S2S(dst, src, 1024u, mb);
                }
            }

            // ---- h to gmem for score GEMM (tid < 64) ----
            if (tid < 64) {
                float4 o;
                o.x = sm.hstage[ch][p][(skq * 4 + 0) * 8 + sb];
                o.y = sm.hstage[ch][p][(skq * 4 + 1) * 8 + sb];
                o.z = sm.hstage[ch][p][(skq * 4 + 2) * 8 + sb];
                o.w = sm.hstage[ch][p][(skq * 4 + 3) * 8 + sb];
                int tOut = dir ? (T_LEN - 1 - s) : s;
                *reinterpret_cast<float4*>(
                    &g_h[(size_t)tOut * B_SZ + b0[ch] + sb][dir * H_DIM + cr * 32 + skq * 4]) = o;
            }
        }
    }

    CLUSTER_SYNC();
    if (tid == 0) {
#pragma unroll
        for (int ch = 0; ch < 2; ++ch) {
            MBAR_INVAL(fullL[ch][0]); MBAR_INVAL(fullL[ch][1]);
            MBAR_INVAL(goL[ch][0]);   MBAR_INVAL(goL[ch][1]);
        }
    }
}

// =====================================================================
// Kernel S: emission scores GEMM (unchanged).
// =====================================================================
__global__ void __launch_bounds__(256) kS(
    const float* __restrict__ Wlin, const float* __restrict__ blin)
{
    __shared__ float As[32][132];
    __shared__ float Bs[32][68];

    const int tid = threadIdx.x;
    const int mBase = blockIdx.x * 128;

    const int ty = tid >> 4;
    const int tx = tid & 15;

    ull acc[4][4];
#pragma unroll
    for (int m = 0; m < 4; m++)
#pragma unroll
        for (int j = 0; j < 4; j++) acc[m][j] = 0ull;

    const int arow = tid >> 3, akq = tid & 7;
    const int bn = tid >> 2, bkq = tid & 3;

    for (int kt = 0; kt < 16; ++kt) {
#pragma unroll
        for (int rr = 0; rr < 4; ++rr) {
            int r = arow + rr * 32;
            const float4 v = *reinterpret_cast<const float4*>(
                &g_h[mBase + r][kt * 32 + akq * 4]);
            As[akq * 4 + 0][r] = v.x; As[akq * 4 + 1][r] = v.y;
            As[akq * 4 + 2][r] = v.z; As[akq * 4 + 3][r] = v.w;
        }
#pragma unroll
        for (int hh = 0; hh < 2; ++hh) {
            const float4 v = *reinterpret_cast<const float4*>(
                &Wlin[(size_t)bn * (2 * H_DIM) + kt * 32 + bkq * 8 + hh * 4]);
            Bs[bkq * 8 + hh * 4 + 0][bn] = v.x; Bs[bkq * 8 + hh * 4 + 1][bn] = v.y;
            Bs[bkq * 8 + hh * 4 + 2][bn] = v.z; Bs[bkq * 8 + hh * 4 + 3][bn] = v.w;
        }
        __syncthreads();
#pragma unroll 8
        for (int k = 0; k < 32; ++k) {
            float4 a0 = *reinterpret_cast<const float4*>(&As[k][ty * 8]);
            float4 a1 = *reinterpret_cast<const float4*>(&As[k][ty * 8 + 4]);
            float4 b4 = *reinterpret_cast<const float4*>(&Bs[k][tx * 4]);
            ull ap[4] = {pk2(a0.x, a0.y), pk2(a0.z, a0.w), pk2(a1.x, a1.y), pk2(a1.z, a1.w)};
            ull bd[4] = {pk2(b4.x, b4.x), pk2(b4.y, b4.y), pk2(b4.z, b4.z), pk2(b4.w, b4.w)};
#pragma unroll
            for (int m = 0; m < 4; ++m)
#pragma unroll
                for (int j = 0; j < 4; ++j)
                    acc[m][j] = fma2_(ap[m], bd[j], acc[m][j]);
        }
        __syncthreads();
    }

    const int n0 = tx * 4;
    float bias[4];
#pragma unroll
    for (int j = 0; j < 4; ++j) bias[j] = blin[n0 + j];
#pragma unroll
    for (int m = 0; m < 4; ++m) {
        float lo[4], hi[4];
#pragma unroll
        for (int j = 0; j < 4; ++j) upk2(acc[m][j], lo[j], hi[j]);
        int row0 = mBase + ty * 8 + 2 * m;
#pragma unroll
        for (int r = 0; r < 2; ++r) {
            const float* src = r ? hi : lo;
            float4 o = make_float4(src[0] + bias[0], src[1] + bias[1],
                                   src[2] + bias[2], src[3] + bias[3]);
            *reinterpret_cast<float4*>(&g_sc[row0 + r][n0]) = o;
        }
    }
}

// =====================================================================
// Kernel C: Viterbi DP + backtrace (unchanged from R4).
// =====================================================================
__global__ void __launch_bounds__(512) kC(
    const float* __restrict__ pw,
    const float* __restrict__ startv, const float* __restrict__ stopv,
    float* __restrict__ out)
{
    __shared__ float delta[2][64];
    __shared__ float fin[64];
    __shared__ unsigned char bp[T_LEN - 1][64];

    const int b = blockIdx.x;
    const int tid = threadIdx.x;
    const int s = tid >> 3;      // state 0..63
    const int p = tid & 7;       // part 0..7 (prev states p*8..p*8+7)

    float Pr[8];
#pragma unroll
    for (int i = 0; i < 8; ++i) Pr[i] = pw[(p * 8 + i) * 64 + s];

    if (p == 0) delta[0][s] = startv[s] + g_sc[b][s];
    __syncthreads();

    float scN = g_sc[(size_t)1 * B_SZ + b][s];
    for (int t = 1; t < T_LEN; ++t) {
        const int pp = (t - 1) & 1, qq = t & 1;
        float4 d0 = *reinterpret_cast<const float4*>(&delta[pp][p * 8]);
        float4 d1 = *reinterpret_cast<const float4*>(&delta[pp][p * 8 + 4]);
        float dv[8] = {d0.x, d0.y, d0.z, d0.w, d1.x, d1.y, d1.z, d1.w};

        float best = dv[0] + Pr[0];
        int bi = p * 8;
#pragma unroll
        for (int i = 1; i < 8; ++i) {
            float v = dv[i] + Pr[i];
            if (v > best) { best = v; bi = p * 8 + i; }
        }
#pragma unroll
        for (int off = 1; off < 8; off <<= 1) {
            float ov = __shfl_xor_sync(0xffffffffu, best, off);
            int oi = __shfl_xor_sync(0xffffffffu, bi, off);
            if (ov > best || (ov == best && oi < bi)) { best = ov; bi = oi; }
        }

        const float sc = scN;
        if (t < T_LEN - 1) scN = g_sc[(size_t)(t + 1) * B_SZ + b][s];

        if (p == 0) {
            bp[t - 1][s] = (unsigned char)bi;
            delta[qq][s] = best + sc;
        }
        __syncthreads();
    }

    if (p == 0) fin[s] = delta[(T_LEN - 1) & 1][s] + stopv[s];
    __syncthreads();

    if (tid == 0) {
        float best = fin[0]; int bi0 = 0;
        for (int i = 1; i < 64; ++i) if (fin[i] > best) { best = fin[i]; bi0 = i; }
        out[b] = best;
        int st = bi0;
        out[64 + (size_t)(T_LEN - 1) * B_SZ + b] = (float)st;
        for (int tt = T_LEN - 2; tt >= 0; --tt) {
            st = bp[tt][st];
            out[64 + (size_t)tt * B_SZ + b] = (float)st;
        }
    }
}

// =====================================================================
extern "C" void kernel_launch(void* const* d_in, const int* in_sizes, int n_in,
                              void* d_out, int out_size)
{
    const int*   obs  = (const int*)  d_in[0];
    const float* h0   = (const float*)d_in[1];
    const float* c0   = (const float*)d_in[2];
    const float* emb  = (const float*)d_in[3];
    const float* WihF = (const float*)d_in[4];
    const float* WhhF = (const float*)d_in[5];
    const float* bihF = (const float*)d_in[6];
    const float* bhhF = (const float*)d_in[7];
    const float* WihB = (const float*)d_in[8];
    const float* WhhB = (const float*)d_in[9];
    const float* bihB = (const float*)d_in[10];
    const float* bhhB = (const float*)d_in[11];
    const float* Wlin = (const float*)d_in[12];
    const float* blin = (const float*)d_in[13];
    const float* pw   = (const float*)d_in[14];
    const float* stv  = (const float*)d_in[15];
    const float* spv  = (const float*)d_in[16];
    float* out = (float*)d_out;

    const int smemB = (int)sizeof(SmemB);
    cudaFuncSetAttribute(kB, cudaFuncAttributeMaxDynamicSharedMemorySize, smemB);

    kA<<<dim3(256, 32), 256>>>(obs, emb, WihF, WihB, bihF, bhhF, bihB, bhhB);
    kB<<<64, 512, smemB>>>(WhhF, WhhB, h0, c0);
    kS<<<256, 256>>>(Wlin, blin);
    kC<<<64, 512>>>(pw, stv, spv, out);
}